// round 2
// baseline (speedup 1.0000x reference)
#include <cuda_runtime.h>
#include <math.h>

#define H_ 256
#define W_ 256
#define NPIX 65536
#define BATCH 2
#define DIM 96
#define C6 576
#define C2 192
#define CHID2 510
#define CHID 255
#define HEADS 4
#define NF 33
#define CPH 48

// two reusable scratch buffers (B*576*65536 floats each)
__device__ float g_bufA[BATCH * C6 * NPIX];
__device__ float g_bufB[BATCH * C6 * NPIX];
// forward twiddles, row stride 65 (padded): (cos, -sin)
__device__ float2 g_tw[NF * 65];

// ---------------- f32x2 helpers ----------------
__device__ __forceinline__ unsigned long long pk2(float x, float y) {
    unsigned long long r;
    asm("mov.b64 %0,{%1,%2};" : "=l"(r) : "f"(x), "f"(y));
    return r;
}
__device__ __forceinline__ void fma2(unsigned long long& d, unsigned long long a, unsigned long long b) {
    asm("fma.rn.f32x2 %0,%1,%2,%0;" : "+l"(d) : "l"(a), "l"(b));
}
__device__ __forceinline__ float2 up2(unsigned long long v) {
    float2 r;
    asm("mov.b64 {%0,%1},%2;" : "=f"(r.x), "=f"(r.y) : "l"(v));
    return r;
}

// ---------------- twiddle init ----------------
__global__ void init_tw_k() {
    int idx = blockIdx.x * blockDim.x + threadIdx.x;
    if (idx >= NF * 65) return;
    int f = idx / 65, n = idx % 65;
    if (n < 64) {
        float s, c;
        sincospif((float)(f * n) * 0.03125f, &s, &c);  // sin/cos(2*pi*f*n/64)
        g_tw[idx] = make_float2(c, -s);
    } else {
        g_tw[idx] = make_float2(0.f, 0.f);
    }
}

// ---------------- fused (optional LN / gate) 1x1 conv ----------------
// layout: in (b, CRAW, 65536); out (b, cout, 65536). TILE_P = 128, block 256.
// thread = 4 couts x 4 pixels, f32x2 inner loop.
template <int CIN, int CRAW, bool LN, bool GATED, bool RESID>
__global__ void conv1x1_k(const float* __restrict__ in, const float* __restrict__ w,
                          const float* __restrict__ lnw, const float* __restrict__ resid,
                          float* __restrict__ out, int cout) {
    extern __shared__ float sm[];
    float* s_in = sm;                   // CIN*128
    float* s_wt = sm + CIN * 128;       // CIN*34  (transposed weights, padded)
    float* s_istd = s_wt + CIN * 34;    // 128
    const int tid = threadIdx.x;
    const int b = blockIdx.x >> 9;            // 512 tiles per image
    const int p0 = (blockIdx.x & 511) * 128;

    for (int idx = tid; idx < CIN * 128; idx += 256) {
        int c = idx >> 7, p = idx & 127;
        if (GATED) {
            float t1 = in[(b * CRAW + c) * NPIX + p0 + p];
            float t2 = in[(b * CRAW + c + CIN) * NPIX + p0 + p];
            float g = 0.5f * t1 * (1.0f + erff(t1 * 0.70710678118654752f));
            s_in[idx] = g * t2;
        } else {
            s_in[idx] = in[(b * CRAW + c) * NPIX + p0 + p];
        }
    }
    __syncthreads();

    if (LN) {
        if (tid < 128) {
            float s = 0.f, s2 = 0.f;
            for (int c = 0; c < CIN; ++c) {
                float v = s_in[c * 128 + tid];
                s += v;
                s2 = fmaf(v, v, s2);
            }
            float m = s * (1.0f / CIN);
            float var = s2 * (1.0f / CIN) - m * m;
            s_istd[tid] = rsqrtf(var + 1e-5f);
        }
        __syncthreads();
        for (int idx = tid; idx < CIN * 128; idx += 256) {
            int c = idx >> 7, p = idx & 127;
            s_in[idx] *= s_istd[p] * __ldg(&lnw[c]);
        }
        __syncthreads();
    }

    const int co_lane = tid & 7;   // 8 lanes * 4 couts = 32 couts per chunk
    const int pg = tid >> 3;       // 32 groups * 4 px = 128 px
    const int pxb = pg * 4;

    for (int co0 = 0; co0 < cout; co0 += 32) {
        // stage transposed weights: s_wt[c*34 + j] = w[(co0+j)*CIN + c]
        #pragma unroll 4
        for (int j = 0; j < 32; ++j) {
            int co = co0 + j;
            for (int c = tid; c < CIN; c += 256)
                s_wt[c * 34 + j] = (co < cout) ? w[co * CIN + c] : 0.0f;
        }
        __syncthreads();

        unsigned long long acc[4][2];
        #pragma unroll
        for (int i = 0; i < 4; ++i) { acc[i][0] = 0ull; acc[i][1] = 0ull; }

        #pragma unroll 4
        for (int c = 0; c < CIN; ++c) {
            float2 wA = *(const float2*)&s_wt[c * 34 + co_lane * 4];
            float2 wB = *(const float2*)&s_wt[c * 34 + co_lane * 4 + 2];
            float2 iA = *(const float2*)&s_in[c * 128 + pxb];
            float2 iB = *(const float2*)&s_in[c * 128 + pxb + 2];
            unsigned long long pa = pk2(iA.x, iA.y), pb = pk2(iB.x, iB.y);
            unsigned long long w0 = pk2(wA.x, wA.x), w1 = pk2(wA.y, wA.y);
            unsigned long long w2 = pk2(wB.x, wB.x), w3 = pk2(wB.y, wB.y);
            fma2(acc[0][0], w0, pa); fma2(acc[0][1], w0, pb);
            fma2(acc[1][0], w1, pa); fma2(acc[1][1], w1, pb);
            fma2(acc[2][0], w2, pa); fma2(acc[2][1], w2, pb);
            fma2(acc[3][0], w3, pa); fma2(acc[3][1], w3, pb);
        }
        __syncthreads();  // s_wt reused next chunk

        #pragma unroll
        for (int i = 0; i < 4; ++i) {
            int co = co0 + co_lane * 4 + i;
            if (co >= cout) continue;
            float2 rA = up2(acc[i][0]), rB = up2(acc[i][1]);
            int base = (b * cout + co) * NPIX + p0 + pxb;
            if (RESID) {
                out[base + 0] = rA.x + resid[base + 0];
                out[base + 1] = rA.y + resid[base + 1];
                out[base + 2] = rB.x + resid[base + 2];
                out[base + 3] = rB.y + resid[base + 3];
            } else {
                out[base + 0] = rA.x; out[base + 1] = rA.y;
                out[base + 2] = rB.x; out[base + 3] = rB.y;
            }
        }
    }
}

// ---------------- depthwise 3x3 (pad 1) ----------------
__global__ void dwconv_k(const float* __restrict__ in, const float* __restrict__ wd,
                         float* __restrict__ out, int C) {
    __shared__ float s[10][34];
    int bc = blockIdx.x >> 8;   // (b*C + c)
    int t = blockIdx.x & 255;
    int ty = t >> 3, tx = t & 7;
    int y0 = ty * 8, x0 = tx * 32;
    const float* base = in + (size_t)bc * NPIX;
    int tid = threadIdx.y * 32 + threadIdx.x;
    for (int idx = tid; idx < 340; idx += 256) {
        int yy = idx / 34, xx = idx % 34;
        int gy = y0 + yy - 1, gx = x0 + xx - 1;
        s[yy][xx] = (gy >= 0 && gy < H_ && gx >= 0 && gx < W_) ? base[gy * W_ + gx] : 0.0f;
    }
    __syncthreads();
    int c = bc % C;
    float acc = 0.f;
    #pragma unroll
    for (int ky = 0; ky < 3; ++ky)
        #pragma unroll
        for (int kx = 0; kx < 3; ++kx)
            acc = fmaf(s[threadIdx.y + ky][threadIdx.x + kx], __ldg(&wd[c * 9 + ky * 3 + kx]), acc);
    out[(size_t)bc * NPIX + (y0 + threadIdx.y) * W_ + x0 + threadIdx.x] = acc;
}

// ---------------- windowed FFT attention, one block per window ----------------
// hid: (b, 576, 256, 256)  q=[0:192) k=[192:384) v=[384:576)
// outp: (b, 192, 256, 256)
__global__ void attn_k(const float* __restrict__ hid, const float* __restrict__ temp,
                       float* __restrict__ outp) {
    extern __shared__ float sm[];
    float2* s_tw = (float2*)sm;            // 33*65
    float2* s_sp = s_tw + NF * 65;         // 3*48*33
    float2* s_A = s_sp + 3 * CPH * NF;     // 33*33
    float* s_nrm = (float*)(s_A + NF * NF);// 33 (padded to 64)
    float* s_raw = s_nrm + 64;             // 48*64

    const int tid = threadIdx.x;
    int wi = blockIdx.x;
    int b = wi >> 12;
    int head = (wi >> 10) & 3;
    int p = wi & 1023;
    int gy0 = (p >> 5) * 8, gx0 = (p & 31) * 8;

    for (int i = tid; i < NF * 65; i += 256) s_tw[i] = g_tw[i];

    // forward rfft of q,k,v via direct DFT (f32x2 (re,im) accumulation)
    for (int t = 0; t < 3; ++t) {
        for (int i = tid; i < CPH * 64; i += 256) {
            int c = i >> 6, n = i & 63;
            int ch = t * C2 + head * CPH + c;
            s_raw[i] = hid[(b * C6 + ch) * NPIX + (gy0 + (n >> 3)) * W_ + gx0 + (n & 7)];
        }
        __syncthreads();
        for (int o = tid; o < CPH * NF; o += 256) {
            int c = o / NF, f = o - c * NF;
            unsigned long long acc = 0ull;
            const float* rw = &s_raw[c * 64];
            const float2* tw = &s_tw[f * 65];
            #pragma unroll 8
            for (int n = 0; n < 64; ++n) {
                float sv = rw[n];
                float2 t2 = tw[n];
                fma2(acc, pk2(sv, sv), pk2(t2.x, t2.y));
            }
            s_sp[t * CPH * NF + o] = up2(acc);
        }
        __syncthreads();
    }

    float tempv = __ldg(&temp[head]);

    // A[f,g] = sum_c Qhat[c,f] * Khat[c,g]   (plain complex product, no conj)
    for (int o = tid; o < NF * NF; o += 256) {
        int f = o / NF, g = o - f * NF;
        float ar = 0.f, ai = 0.f;
        const float2* q = s_sp;
        const float2* k = s_sp + CPH * NF;
        for (int c = 0; c < CPH; ++c) {
            float2 qc = q[c * NF + f], kc = k[c * NF + g];
            ar = fmaf(qc.x, kc.x, ar); ar = fmaf(-qc.y, kc.y, ar);
            ai = fmaf(qc.x, kc.y, ai); ai = fmaf(qc.y, kc.x, ai);
        }
        s_A[o] = make_float2(ar * tempv, ai * tempv);
    }
    __syncthreads();

    // per-row complex L2 norm over g
    if (tid < NF) {
        float ssum = 0.f;
        for (int g = 0; g < NF; ++g) {
            float2 a = s_A[tid * NF + g];
            ssum = fmaf(a.x, a.x, fmaf(a.y, a.y, ssum));
        }
        s_nrm[tid] = rsqrtf(ssum);
    }
    __syncthreads();

    // Ohat[c,f] = (sum_g A[f,g]*Vhat[c,g]) * invnrm[f]   -> overwrite s_sp[0]
    for (int o = tid; o < CPH * NF; o += 256) {
        int c = o / NF, f = o - c * NF;
        float orr = 0.f, oi = 0.f;
        const float2* v = s_sp + 2 * CPH * NF + c * NF;
        const float2* arow = &s_A[f * NF];
        for (int g = 0; g < NF; ++g) {
            float2 a = arow[g], vv = v[g];
            orr = fmaf(a.x, vv.x, orr); orr = fmaf(-a.y, vv.y, orr);
            oi = fmaf(a.x, vv.y, oi);   oi = fmaf(a.y, vv.x, oi);
        }
        float inv = s_nrm[f];
        s_sp[o] = make_float2(orr * inv, oi * inv);
    }
    __syncthreads();

    // irfft(n=64): x[n] = (Re0 + (-1)^n Re32 + 2*sum_{1..31}(Re*cos - Im*(-(-sin)))) / 64
    // tw = (cos, -sin) so each term is (Re*tw.x + Im*tw.y); Im of bins 0/32 vanish (tw.y=0).
    for (int i = tid; i < CPH * 64; i += 256) {
        int c = i >> 6, n = i & 63;
        const float2* orow = &s_sp[c * NF];
        float2 o0 = orow[0];
        float2 t32 = s_tw[32 * 65 + n];
        float2 o32 = orow[32];
        float ends = o0.x + o32.x * t32.x;
        float mid = 0.f;
        #pragma unroll 8
        for (int f = 1; f < 32; ++f) {
            float2 tf = s_tw[f * 65 + n], of = orow[f];
            mid = fmaf(of.x, tf.x, mid);
            mid = fmaf(of.y, tf.y, mid);
        }
        float res = (ends + 2.0f * mid) * (1.0f / 64.0f);
        int ch = head * CPH + c;
        outp[(b * C2 + ch) * NPIX + (gy0 + (n >> 3)) * W_ + gx0 + (n & 7)] = res;
    }
}

// ---------------- launch ----------------
extern "C" void kernel_launch(void* const* d_in, const int* in_sizes, int n_in,
                              void* d_out, int out_size) {
    const float* x = (const float*)d_in[0];
    const float* th_w = (const float*)d_in[1];
    const float* th_dw = (const float*)d_in[2];
    const float* po_w = (const float*)d_in[3];
    const float* temp = (const float*)d_in[4];
    const float* n1 = (const float*)d_in[5];
    const float* n2 = (const float*)d_in[6];
    const float* fi_w = (const float*)d_in[7];
    const float* f_dw = (const float*)d_in[8];
    const float* fo_w = (const float*)d_in[9];
    float* out = (float*)d_out;

    float *bufA, *bufB;
    cudaGetSymbolAddress((void**)&bufA, g_bufA);
    cudaGetSymbolAddress((void**)&bufB, g_bufB);

    const int smA = (96 * 128 + 96 * 34 + 128) * 4;    // 62720
    const int smB = (192 * 128 + 192 * 34 + 128) * 4;  // 124928
    const int smD = (255 * 128 + 255 * 34 + 128) * 4;  // 165752
    const int smAt = (NF * 65 * 2 + 3 * CPH * NF * 2 + NF * NF * 2 + 64 + CPH * 64) * 4;

    cudaFuncSetAttribute((const void*)conv1x1_k<96, 96, true, false, false>,
                         cudaFuncAttributeMaxDynamicSharedMemorySize, smA);
    cudaFuncSetAttribute((const void*)conv1x1_k<192, 192, false, false, true>,
                         cudaFuncAttributeMaxDynamicSharedMemorySize, smB);
    cudaFuncSetAttribute((const void*)conv1x1_k<255, 510, false, true, true>,
                         cudaFuncAttributeMaxDynamicSharedMemorySize, smD);
    cudaFuncSetAttribute((const void*)attn_k,
                         cudaFuncAttributeMaxDynamicSharedMemorySize, smAt);

    const int NTILE = BATCH * NPIX / 128;  // 1024

    init_tw_k<<<(NF * 65 + 255) / 256, 256>>>();

    // attn branch: LN1 + to_hidden 96->576
    conv1x1_k<96, 96, true, false, false><<<NTILE, 256, smA>>>(x, th_w, n1, nullptr, bufA, C6);
    dwconv_k<<<BATCH * C6 * 256, dim3(32, 8)>>>(bufA, th_dw, bufB, C6);
    attn_k<<<BATCH * HEADS * 1024, 256, smAt>>>(bufB, temp, bufA);
    // project_out 192->96 + residual x  -> d_out
    conv1x1_k<192, 192, false, false, true><<<NTILE, 256, smB>>>(bufA, po_w, nullptr, x, out, DIM);

    // ffn branch: LN2 + ffn_in 96->510
    conv1x1_k<96, 96, true, false, false><<<NTILE, 256, smA>>>(out, fi_w, n2, nullptr, bufB, CHID2);
    dwconv_k<<<BATCH * CHID2 * 256, dim3(32, 8)>>>(bufB, f_dw, bufA, CHID2);
    // gelu(x1)*x2 gated, 255->96 + residual d_out -> d_out
    conv1x1_k<255, 510, false, true, true><<<NTILE, 256, smD>>>(bufA, fo_w, nullptr, out, out, DIM);

    (void)in_sizes; (void)n_in; (void)out_size;
}

// round 3
// speedup vs baseline: 2.6261x; 2.6261x over previous
#include <cuda_runtime.h>
#include <math.h>

#define H_ 256
#define W_ 256
#define NPIX 65536
#define BATCH 2
#define DIM 96
#define C6 576
#define C2 192
#define CHID2 510
#define CHID 255
#define HEADS 4
#define NF 33
#define CPH 48

// scratch
__device__ float g_bufA[BATCH * C6 * NPIX];
__device__ float g_bufB[BATCH * C6 * NPIX];
__device__ float g_istd[BATCH * NPIX];
__device__ float2 g_twF[NF * 64];    // [f][n] = (cos, -sin)(2pi f n/64)
__device__ float2 g_twT[64 * 34];    // [n][f], f=33 pad = 0

// ---------------- f32x2 helpers ----------------
typedef unsigned long long ull;
__device__ __forceinline__ ull pk2(float x, float y) {
    ull r; asm("mov.b64 %0,{%1,%2};" : "=l"(r) : "f"(x), "f"(y)); return r;
}
__device__ __forceinline__ void fma2(ull& d, ull a, ull b) {
    asm("fma.rn.f32x2 %0,%1,%2,%0;" : "+l"(d) : "l"(a), "l"(b));
}
__device__ __forceinline__ float2 up2(ull v) {
    float2 r; asm("mov.b64 {%0,%1},%2;" : "=f"(r.x), "=f"(r.y) : "l"(v)); return r;
}

// ---------------- twiddle init ----------------
__global__ void init_tw_k() {
    int idx = blockIdx.x * blockDim.x + threadIdx.x;
    if (idx < NF * 64) {
        int f = idx >> 6, n = idx & 63;
        float s, c;
        sincospif((float)(f * n) * (1.0f / 32.0f), &s, &c);
        g_twF[idx] = make_float2(c, -s);
    }
    if (idx < 64 * 34) {
        int n = idx / 34, f = idx % 34;
        if (f < NF) {
            float s, c;
            sincospif((float)(f * n) * (1.0f / 32.0f), &s, &c);
            g_twT[idx] = make_float2(c, -s);
        } else {
            g_twT[idx] = make_float2(0.f, 0.f);
        }
    }
}

// ---------------- per-pixel inv-std (bias-free LN) ----------------
__global__ void istd_k(const float* __restrict__ in, float* __restrict__ istd) {
    int p = blockIdx.x * 256 + threadIdx.x;        // [0, BATCH*NPIX)
    int b = p >> 16, px = p & 65535;
    const float* base = in + (size_t)b * DIM * NPIX + px;
    float s = 0.f, s2 = 0.f;
    #pragma unroll 8
    for (int c = 0; c < DIM; ++c) {
        float v = __ldg(&base[c * NPIX]);
        s += v; s2 = fmaf(v, v, s2);
    }
    float m = s * (1.0f / DIM);
    float var = s2 * (1.0f / DIM) - m * m;
    istd[p] = rsqrtf(var + 1e-5f);
}

// ---------------- SGEMM-style 1x1 conv ----------------
// out[b,co,p] = sum_c w[co,c] * f(in)[b,c,p]  (+ LN scaling / gelu gate / residual)
template <int BM, int THREADS, int CIN, bool LN, bool GATED, bool RESID>
__global__ __launch_bounds__(THREADS, 2)
void gemm_conv_k(const float* __restrict__ in, const float* __restrict__ w,
                 const float* __restrict__ lnw, const float* __restrict__ istd,
                 const float* __restrict__ resid, float* __restrict__ out,
                 int cout, int mtiles) {
    constexpr int BN = 128, BK = 8;
    constexpr int CINRAW = GATED ? 2 * CIN : CIN;
    constexpr int NB4 = (BK * BN / 4 + THREADS - 1) / THREADS;  // float4 B-loads per thread
    __shared__ float s_a[2][BK][BM];
    __shared__ float s_b[2][BK][BN];

    const int tid = threadIdx.x;
    int bid = blockIdx.x;
    const int mt = bid % mtiles; bid /= mtiles;
    const int nt = bid & 511;
    const int b = bid >> 9;
    const int p0 = nt * BN;
    const int co0 = mt * BM;

    // A-load mapping: 4 scalars per thread
    const int a_co = tid >> 1;
    const int a_k4 = (tid & 1) * 4;
    const bool a_cov = (co0 + a_co) < cout;

    const int tr = tid >> 4;      // BM/8 rows of threads
    const int tc = tid & 15;      // 16 cols

    const int NC = (CIN + BK - 1) / BK;

    float areg[4];
    float4 breg[NB4];

    // ---- load helpers (as lambdas) ----
    auto loadA = [&](int ch) {
        int c0 = ch * BK;
        #pragma unroll
        for (int i = 0; i < 4; ++i) {
            int c = c0 + a_k4 + i;
            areg[i] = (a_cov && c < CIN) ? __ldg(&w[(co0 + a_co) * CIN + c]) : 0.0f;
        }
    };
    auto loadB = [&](int ch) {
        int c0 = ch * BK;
        #pragma unroll
        for (int j = 0; j < NB4; ++j) {
            int i = tid + j * THREADS;
            float4 v = make_float4(0.f, 0.f, 0.f, 0.f);
            if (i < BK * BN / 4) {
                int k = i >> 5, px4 = (i & 31) * 4;
                int c = c0 + k;
                if (c < CIN) {
                    if (GATED) {
                        float4 t1 = *(const float4*)&in[((size_t)b * CINRAW + c) * NPIX + p0 + px4];
                        float4 t2 = *(const float4*)&in[((size_t)b * CINRAW + c + CIN) * NPIX + p0 + px4];
                        v.x = 0.5f * t1.x * (1.0f + erff(t1.x * 0.70710678118654752f)) * t2.x;
                        v.y = 0.5f * t1.y * (1.0f + erff(t1.y * 0.70710678118654752f)) * t2.y;
                        v.z = 0.5f * t1.z * (1.0f + erff(t1.z * 0.70710678118654752f)) * t2.z;
                        v.w = 0.5f * t1.w * (1.0f + erff(t1.w * 0.70710678118654752f)) * t2.w;
                    } else {
                        v = *(const float4*)&in[((size_t)b * CINRAW + c) * NPIX + p0 + px4];
                        if (LN) {
                            float lw = __ldg(&lnw[c]);
                            float4 is = *(const float4*)&istd[b * NPIX + p0 + px4];
                            v.x *= is.x * lw; v.y *= is.y * lw;
                            v.z *= is.z * lw; v.w *= is.w * lw;
                        }
                    }
                }
            }
            breg[j] = v;
        }
    };
    auto storeAB = [&](int buf) {
        #pragma unroll
        for (int i = 0; i < 4; ++i) s_a[buf][a_k4 + i][a_co] = areg[i];
        #pragma unroll
        for (int j = 0; j < NB4; ++j) {
            int i = tid + j * THREADS;
            if (i < BK * BN / 4) {
                int k = i >> 5, px4 = (i & 31) * 4;
                *(float4*)&s_b[buf][k][px4] = breg[j];
            }
        }
    };

    loadA(0); loadB(0);
    storeAB(0);
    __syncthreads();

    ull acc[8][4];
    #pragma unroll
    for (int i = 0; i < 8; ++i)
        #pragma unroll
        for (int j = 0; j < 4; ++j) acc[i][j] = 0ull;

    for (int ch = 0; ch < NC; ++ch) {
        if (ch + 1 < NC) { loadA(ch + 1); loadB(ch + 1); }
        int buf = ch & 1;
        #pragma unroll
        for (int k = 0; k < BK; ++k) {
            float4 a0 = *(const float4*)&s_a[buf][k][tr * 8];
            float4 a1 = *(const float4*)&s_a[buf][k][tr * 8 + 4];
            ulonglong2 b0 = *(const ulonglong2*)&s_b[buf][k][tc * 8];
            ulonglong2 b1 = *(const ulonglong2*)&s_b[buf][k][tc * 8 + 4];
            ull pa0 = pk2(a0.x, a0.x), pa1 = pk2(a0.y, a0.y);
            ull pa2 = pk2(a0.z, a0.z), pa3 = pk2(a0.w, a0.w);
            ull pa4 = pk2(a1.x, a1.x), pa5 = pk2(a1.y, a1.y);
            ull pa6 = pk2(a1.z, a1.z), pa7 = pk2(a1.w, a1.w);
            fma2(acc[0][0], pa0, b0.x); fma2(acc[0][1], pa0, b0.y); fma2(acc[0][2], pa0, b1.x); fma2(acc[0][3], pa0, b1.y);
            fma2(acc[1][0], pa1, b0.x); fma2(acc[1][1], pa1, b0.y); fma2(acc[1][2], pa1, b1.x); fma2(acc[1][3], pa1, b1.y);
            fma2(acc[2][0], pa2, b0.x); fma2(acc[2][1], pa2, b0.y); fma2(acc[2][2], pa2, b1.x); fma2(acc[2][3], pa2, b1.y);
            fma2(acc[3][0], pa3, b0.x); fma2(acc[3][1], pa3, b0.y); fma2(acc[3][2], pa3, b1.x); fma2(acc[3][3], pa3, b1.y);
            fma2(acc[4][0], pa4, b0.x); fma2(acc[4][1], pa4, b0.y); fma2(acc[4][2], pa4, b1.x); fma2(acc[4][3], pa4, b1.y);
            fma2(acc[5][0], pa5, b0.x); fma2(acc[5][1], pa5, b0.y); fma2(acc[5][2], pa5, b1.x); fma2(acc[5][3], pa5, b1.y);
            fma2(acc[6][0], pa6, b0.x); fma2(acc[6][1], pa6, b0.y); fma2(acc[6][2], pa6, b1.x); fma2(acc[6][3], pa6, b1.y);
            fma2(acc[7][0], pa7, b0.x); fma2(acc[7][1], pa7, b0.y); fma2(acc[7][2], pa7, b1.x); fma2(acc[7][3], pa7, b1.y);
        }
        if (ch + 1 < NC) storeAB(buf ^ 1);
        __syncthreads();
    }

    #pragma unroll
    for (int i = 0; i < 8; ++i) {
        int co = co0 + tr * 8 + i;
        if (co >= cout) continue;
        size_t rowb = ((size_t)b * cout + co) * NPIX + p0 + tc * 8;
        #pragma unroll
        for (int j = 0; j < 4; ++j) {
            float2 r = up2(acc[i][j]);
            if (RESID) {
                float2 rs = *(const float2*)&resid[rowb + j * 2];
                r.x += rs.x; r.y += rs.y;
            }
            *(float2*)&out[rowb + j * 2] = r;
        }
    }
}

// ---------------- depthwise 3x3 (pad 1) ----------------
__global__ void dwconv_k(const float* __restrict__ in, const float* __restrict__ wd,
                         float* __restrict__ out, int C) {
    __shared__ float s[10][34];
    int bc = blockIdx.x >> 8;
    int t = blockIdx.x & 255;
    int ty = t >> 3, tx = t & 7;
    int y0 = ty * 8, x0 = tx * 32;
    const float* base = in + (size_t)bc * NPIX;
    int tid = threadIdx.y * 32 + threadIdx.x;
    for (int idx = tid; idx < 340; idx += 256) {
        int yy = idx / 34, xx = idx % 34;
        int gy = y0 + yy - 1, gx = x0 + xx - 1;
        s[yy][xx] = (gy >= 0 && gy < H_ && gx >= 0 && gx < W_) ? base[gy * W_ + gx] : 0.0f;
    }
    __syncthreads();
    int c = bc % C;
    float acc = 0.f;
    #pragma unroll
    for (int ky = 0; ky < 3; ++ky)
        #pragma unroll
        for (int kx = 0; kx < 3; ++kx)
            acc = fmaf(s[threadIdx.y + ky][threadIdx.x + kx], __ldg(&wd[c * 9 + ky * 3 + kx]), acc);
    out[(size_t)bc * NPIX + (y0 + threadIdx.y) * W_ + x0 + threadIdx.x] = acc;
}

// ---------------- windowed FFT attention ----------------
// smem (floats): s_sp [0,9792) = float2[3][48][34]
// arena at 9792:
//   phase1: twT float2[64][34] (4352 f) | raw float[3][64][48] at +4352 (9216 f)
//   phase2/3 overlay: A float2[33][34] (2244 f) | nrm @+2244 (64 f) | twF float2[33][64] @+2308 (4224 f)
#define SM_FLOATS (9792 + 4352 + 9216)

__global__ __launch_bounds__(256, 2)
void attn_k(const float* __restrict__ hid, const float* __restrict__ temp,
            float* __restrict__ outp) {
    extern __shared__ float sm[];
    float2* s_sp = (float2*)sm;                 // [3][48][34]
    float* arena = sm + 9792;
    float2* twT = (float2*)arena;               // [64][34]
    float* raw = arena + 4352;                  // [3][64][48]
    float2* A = (float2*)arena;                 // [33][34]
    float* nrm = arena + 2244;
    float2* twF = (float2*)(arena + 2308);      // [33][64]

    const int tid = threadIdx.x;
    const int wi = blockIdx.x;
    const int b = wi >> 12;
    const int head = (wi >> 10) & 3;
    const int p = wi & 1023;
    const int gy0 = (p >> 5) << 3, gx0 = (p & 31) << 3;

    for (int i = tid; i < 64 * 34; i += 256) twT[i] = g_twT[i];
    for (int i = tid; i < 3 * CPH * 64; i += 256) {
        int t = i / 3072; int r = i - t * 3072; int c = r >> 6; int n = r & 63;
        float v = hid[((size_t)b * C6 + t * C2 + head * CPH + c) * NPIX + (gy0 + (n >> 3)) * W_ + gx0 + (n & 7)];
        raw[t * 3072 + n * 48 + c] = v;
    }
    __syncthreads();

    // ---- DFT: sp[t][c][f] = sum_n raw[t][n][c] * tw[f][n] ----
    for (int task = tid; task < 306; task += 256) {
        int t = task / 102; int r = task - t * 102;
        int cg = r / 17, fp = r - cg * 17;
        int c0 = cg * 8, f0 = fp * 2;
        ull acc[8][2];
        #pragma unroll
        for (int i = 0; i < 8; ++i) { acc[i][0] = 0ull; acc[i][1] = 0ull; }
        const float* rp = raw + t * 3072 + c0;
        #pragma unroll 4
        for (int n = 0; n < 64; ++n) {
            float4 ra = *(const float4*)(rp + n * 48);
            float4 rb = *(const float4*)(rp + n * 48 + 4);
            ulonglong2 tw = *(const ulonglong2*)&twT[n * 34 + f0];
            ull p0_ = pk2(ra.x, ra.x), p1_ = pk2(ra.y, ra.y), p2_ = pk2(ra.z, ra.z), p3_ = pk2(ra.w, ra.w);
            ull p4_ = pk2(rb.x, rb.x), p5_ = pk2(rb.y, rb.y), p6_ = pk2(rb.z, rb.z), p7_ = pk2(rb.w, rb.w);
            fma2(acc[0][0], p0_, tw.x); fma2(acc[0][1], p0_, tw.y);
            fma2(acc[1][0], p1_, tw.x); fma2(acc[1][1], p1_, tw.y);
            fma2(acc[2][0], p2_, tw.x); fma2(acc[2][1], p2_, tw.y);
            fma2(acc[3][0], p3_, tw.x); fma2(acc[3][1], p3_, tw.y);
            fma2(acc[4][0], p4_, tw.x); fma2(acc[4][1], p4_, tw.y);
            fma2(acc[5][0], p5_, tw.x); fma2(acc[5][1], p5_, tw.y);
            fma2(acc[6][0], p6_, tw.x); fma2(acc[6][1], p6_, tw.y);
            fma2(acc[7][0], p7_, tw.x); fma2(acc[7][1], p7_, tw.y);
        }
        #pragma unroll
        for (int i = 0; i < 8; ++i) {
            s_sp[(t * CPH + c0 + i) * 34 + f0] = up2(acc[i][0]);
            s_sp[(t * CPH + c0 + i) * 34 + f0 + 1] = up2(acc[i][1]);  // f=33 slot: tw pad=0 -> zeros
        }
    }
    __syncthreads();

    // ---- load irfft twiddles (overwrites dead raw/twT tail) + Gram ----
    for (int i = tid; i < NF * 64; i += 256) twF[i] = g_twF[i];

    const float tempv = __ldg(&temp[head]);
    const float2* Q = s_sp;
    const float2* K = s_sp + CPH * 34;
    const float2* V = s_sp + 2 * CPH * 34;

    for (int o = tid; o < 289; o += 256) {
        int f0 = (o / 17) * 2, g0 = (o % 17) * 2;
        float a00r = 0.f, a00i = 0.f, a01r = 0.f, a01i = 0.f;
        float a10r = 0.f, a10i = 0.f, a11r = 0.f, a11i = 0.f;
        #pragma unroll 4
        for (int c = 0; c < CPH; ++c) {
            float4 q = *(const float4*)&Q[c * 34 + f0];
            float4 k = *(const float4*)&K[c * 34 + g0];
            a00r = fmaf(q.x, k.x, a00r); a00r = fmaf(-q.y, k.y, a00r);
            a00i = fmaf(q.x, k.y, a00i); a00i = fmaf(q.y, k.x, a00i);
            a01r = fmaf(q.x, k.z, a01r); a01r = fmaf(-q.y, k.w, a01r);
            a01i = fmaf(q.x, k.w, a01i); a01i = fmaf(q.y, k.z, a01i);
            a10r = fmaf(q.z, k.x, a10r); a10r = fmaf(-q.w, k.y, a10r);
            a10i = fmaf(q.z, k.y, a10i); a10i = fmaf(q.w, k.x, a10i);
            a11r = fmaf(q.z, k.z, a11r); a11r = fmaf(-q.w, k.w, a11r);
            a11i = fmaf(q.z, k.w, a11i); a11i = fmaf(q.w, k.z, a11i);
        }
        A[f0 * 34 + g0] = make_float2(a00r * tempv, a00i * tempv);
        A[f0 * 34 + g0 + 1] = make_float2(a01r * tempv, a01i * tempv);
        if (f0 + 1 < NF) {
            A[(f0 + 1) * 34 + g0] = make_float2(a10r * tempv, a10i * tempv);
            A[(f0 + 1) * 34 + g0 + 1] = make_float2(a11r * tempv, a11i * tempv);
        }
    }
    __syncthreads();

    if (tid < NF) {
        float ssum = 0.f;
        for (int g = 0; g < NF; ++g) {
            float2 a = A[tid * 34 + g];
            ssum = fmaf(a.x, a.x, fmaf(a.y, a.y, ssum));
        }
        nrm[tid] = rsqrtf(ssum);
    }
    __syncthreads();

    // ---- AV: Ohat[c][f] = (sum_g A[f][g] * V[c][g]) * invnrm[f] -> overwrite Q region ----
    for (int o = tid; o < 408; o += 256) {
        int c0 = (o / 17) * 2, f0 = (o % 17) * 2;
        const float2* Ar0 = &A[f0 * 34];
        const float2* Ar1 = &A[((f0 + 1 < NF) ? f0 + 1 : f0) * 34];
        float o00r = 0.f, o00i = 0.f, o01r = 0.f, o01i = 0.f;
        float o10r = 0.f, o10i = 0.f, o11r = 0.f, o11i = 0.f;
        #pragma unroll 4
        for (int g = 0; g < 34; g += 2) {
            float4 a0 = *(const float4*)&Ar0[g];
            float4 a1 = *(const float4*)&Ar1[g];
            float4 v0 = *(const float4*)&V[c0 * 34 + g];
            float4 v1 = *(const float4*)&V[(c0 + 1) * 34 + g];
            o00r = fmaf(a0.x, v0.x, o00r); o00r = fmaf(-a0.y, v0.y, o00r);
            o00i = fmaf(a0.x, v0.y, o00i); o00i = fmaf(a0.y, v0.x, o00i);
            o00r = fmaf(a0.z, v0.z, o00r); o00r = fmaf(-a0.w, v0.w, o00r);
            o00i = fmaf(a0.z, v0.w, o00i); o00i = fmaf(a0.w, v0.z, o00i);
            o01r = fmaf(a1.x, v0.x, o01r); o01r = fmaf(-a1.y, v0.y, o01r);
            o01i = fmaf(a1.x, v0.y, o01i); o01i = fmaf(a1.y, v0.x, o01i);
            o01r = fmaf(a1.z, v0.z, o01r); o01r = fmaf(-a1.w, v0.w, o01r);
            o01i = fmaf(a1.z, v0.w, o01i); o01i = fmaf(a1.w, v0.z, o01i);
            o10r = fmaf(a0.x, v1.x, o10r); o10r = fmaf(-a0.y, v1.y, o10r);
            o10i = fmaf(a0.x, v1.y, o10i); o10i = fmaf(a0.y, v1.x, o10i);
            o10r = fmaf(a0.z, v1.z, o10r); o10r = fmaf(-a0.w, v1.w, o10r);
            o10i = fmaf(a0.z, v1.w, o10i); o10i = fmaf(a0.w, v1.z, o10i);
            o11r = fmaf(a1.x, v1.x, o11r); o11r = fmaf(-a1.y, v1.y, o11r);
            o11i = fmaf(a1.x, v1.y, o11i); o11i = fmaf(a1.y, v1.x, o11i);
            o11r = fmaf(a1.z, v1.z, o11r); o11r = fmaf(-a1.w, v1.w, o11r);
            o11i = fmaf(a1.z, v1.w, o11i); o11i = fmaf(a1.w, v1.z, o11i);
        }
        float inv0 = nrm[f0];
        float inv1 = (f0 + 1 < NF) ? nrm[f0 + 1] : 0.f;
        float2* Ow = (float2*)s_sp;   // Q region, dead
        Ow[c0 * 34 + f0] = make_float2(o00r * inv0, o00i * inv0);
        Ow[c0 * 34 + f0 + 1] = make_float2(o01r * inv1, o01i * inv1);
        Ow[(c0 + 1) * 34 + f0] = make_float2(o10r * inv0, o10i * inv0);
        Ow[(c0 + 1) * 34 + f0 + 1] = make_float2(o11r * inv1, o11i * inv1);
    }
    __syncthreads();

    // ---- irfft(n=64): x[n] = (O0.re + O32.re*cos(pi n) + 2*sum_{1..31}(Re*cos + Im*(-sin)))/64 ----
    for (int o = tid; o < 384; o += 256) {
        int c0 = (o >> 5) * 4;
        int n0 = (o & 31) * 2;
        float ends[4][2], mid[4][2];
        float2 t32a = twF[32 * 64 + n0];
        float2 t32b = twF[32 * 64 + n0 + 1];
        #pragma unroll
        for (int c = 0; c < 4; ++c) {
            float o0 = s_sp[(c0 + c) * 34].x;
            float o32 = s_sp[(c0 + c) * 34 + 32].x;
            ends[c][0] = fmaf(o32, t32a.x, o0);
            ends[c][1] = fmaf(o32, t32b.x, o0);
            mid[c][0] = 0.f; mid[c][1] = 0.f;
        }
        #pragma unroll 4
        for (int f = 1; f < 32; ++f) {
            float4 tw = *(const float4*)&twF[f * 64 + n0];  // (n0, n0+1)
            #pragma unroll
            for (int c = 0; c < 4; ++c) {
                float2 of = s_sp[(c0 + c) * 34 + f];
                mid[c][0] = fmaf(of.x, tw.x, mid[c][0]); mid[c][0] = fmaf(of.y, tw.y, mid[c][0]);
                mid[c][1] = fmaf(of.x, tw.z, mid[c][1]); mid[c][1] = fmaf(of.y, tw.w, mid[c][1]);
            }
        }
        #pragma unroll
        for (int c = 0; c < 4; ++c) {
            float r0 = (ends[c][0] + 2.0f * mid[c][0]) * (1.0f / 64.0f);
            float r1 = (ends[c][1] + 2.0f * mid[c][1]) * (1.0f / 64.0f);
            size_t base = ((size_t)b * C2 + head * CPH + c0 + c) * NPIX + (gy0 + (n0 >> 3)) * W_ + gx0 + (n0 & 7);
            *(float2*)&outp[base] = make_float2(r0, r1);
        }
    }
}

// ---------------- launch ----------------
extern "C" void kernel_launch(void* const* d_in, const int* in_sizes, int n_in,
                              void* d_out, int out_size) {
    const float* x = (const float*)d_in[0];
    const float* th_w = (const float*)d_in[1];
    const float* th_dw = (const float*)d_in[2];
    const float* po_w = (const float*)d_in[3];
    const float* temp = (const float*)d_in[4];
    const float* n1 = (const float*)d_in[5];
    const float* n2 = (const float*)d_in[6];
    const float* fi_w = (const float*)d_in[7];
    const float* f_dw = (const float*)d_in[8];
    const float* fo_w = (const float*)d_in[9];
    float* out = (float*)d_out;

    float *bufA, *bufB, *istd;
    cudaGetSymbolAddress((void**)&bufA, g_bufA);
    cudaGetSymbolAddress((void**)&bufB, g_bufB);
    cudaGetSymbolAddress((void**)&istd, g_istd);

    const int smAt = SM_FLOATS * 4;
    cudaFuncSetAttribute((const void*)attn_k, cudaFuncAttributeMaxDynamicSharedMemorySize, smAt);

    init_tw_k<<<10, 256>>>();

    // ---- attention branch ----
    istd_k<<<BATCH * NPIX / 256, 256>>>(x, istd);
    // LN1 + to_hidden 96->576  (5 cout tiles of 128)
    gemm_conv_k<128, 256, 96, true, false, false><<<BATCH * 512 * 5, 256>>>(
        x, th_w, n1, istd, nullptr, bufA, C6, 5);
    dwconv_k<<<BATCH * C6 * 256, dim3(32, 8)>>>(bufA, th_dw, bufB, C6);
    attn_k<<<BATCH * HEADS * 1024, 256, smAt>>>(bufB, temp, bufA);
    // project_out 192->96 + residual x
    gemm_conv_k<96, 192, 192, false, false, true><<<BATCH * 512, 192>>>(
        bufA, po_w, nullptr, nullptr, x, out, DIM, 1);

    // ---- ffn branch ----
    istd_k<<<BATCH * NPIX / 256, 256>>>(out, istd);
    // LN2 + ffn_in 96->510  (4 cout tiles of 128)
    gemm_conv_k<128, 256, 96, true, false, false><<<BATCH * 512 * 4, 256>>>(
        out, fi_w, n2, istd, nullptr, bufB, CHID2, 4);
    dwconv_k<<<BATCH * CHID2 * 256, dim3(32, 8)>>>(bufB, f_dw, bufA, CHID2);
    // gelu(x1)*x2 gated, 255->96 + residual
    gemm_conv_k<96, 192, 255, false, true, true><<<BATCH * 512, 192>>>(
        bufA, fo_w, nullptr, nullptr, out, out, DIM, 1);

    (void)in_sizes; (void)n_in; (void)out_size;
}